// round 2
// baseline (speedup 1.0000x reference)
#include <cuda_runtime.h>

// Problem constants (fixed by the reference)
#define BATCH 16
#define CIN   128
#define COUT  128
#define Hh    224
#define Ww    224
#define PLANE  (Hh * Ww)        // 50176 floats per (b,c) plane
#define PLANE4 (PLANE / 4)      // 12544 float4 per plane

// Tile geometry: 56x56 output tile, 58x58 channel-sum region (1-halo)
#define TR 56
#define TC 56
#define RR 58                   // region rows
#define SS 60                   // smem row stride (floats)
#define NCORE (RR * (TC / 4))   // 58*14 = 812 float4 core slots
#define NEDGE (RR * 2)          // 116 edge scalars
#define NP2   (TR * (TC / 4))   // 56*14 = 784 output float4 slots
#define NT    256               // threads per CTA

__global__ __launch_bounds__(NT) void fused_cross_conv(const float* __restrict__ x,
                                                       const float* __restrict__ bias,
                                                       float* __restrict__ out) {
    __shared__ float Csh[RR * SS];   // channel-sum region
    __shared__ float sb[COUT];

    const int tid = threadIdx.x;
    if (tid < COUT) sb[tid] = bias[tid];

    // Tile decomposition: 16 batches x 4 row-tiles x 4 col-tiles = 256 CTAs
    const int bx = blockIdx.x;
    const int b  = bx >> 4;
    const int t  = bx & 15;
    const int r0 = (t >> 2) * TR;
    const int c0 = (t & 3)  * TC;

    // ---------------- Phase 1: channel sum into smem ----------------
    // Core float4 slots (aligned): region row i in [0,58), col4 j in [0,14)
    //   global row gr = r0-1+i, global col gc = c0 + 4*j  (always in-range)
    int   coff[4];      // plane-relative float4 offset
    bool  cval[4];      // row in range?
    int   csm[4];       // smem float offset
    float4 acc[4];
#pragma unroll
    for (int k = 0; k < 4; k++) {
        int s = tid + k * NT;
        acc[k] = make_float4(0.f, 0.f, 0.f, 0.f);
        if (s < NCORE) {
            int i  = s / (TC / 4);
            int j4 = s - i * (TC / 4);
            int gr = r0 - 1 + i;
            cval[k] = (gr >= 0) && (gr < Hh);
            coff[k] = gr * (Ww / 4) + (c0 >> 2) + j4;
            csm[k]  = i * SS + 1 + 4 * j4;
        } else {
            cval[k] = false;
            coff[k] = 0;
            csm[k]  = -1;
        }
    }
    // Edge scalars: region row i, side 0 (col c0-1) / side 1 (col c0+TC)
    bool  eact = (tid < NEDGE);
    bool  eval = false;
    int   eoff = 0, esm = -1;
    float eacc = 0.f;
    if (eact) {
        int i    = tid >> 1;
        int side = tid & 1;
        int gc   = side ? (c0 + TC) : (c0 - 1);
        int gr   = r0 - 1 + i;
        eval = (gr >= 0) && (gr < Hh) && (gc >= 0) && (gc < Ww);
        eoff = gr * Ww + gc;
        esm  = i * SS + (side ? (TC + 1) : 0);
    }

    const float4* x4b = reinterpret_cast<const float4*>(x) + (size_t)b * CIN * PLANE4;
    const float*  xsb = x + (size_t)b * CIN * PLANE;

#pragma unroll 2
    for (int c = 0; c < CIN; c++) {
        const float4* base = x4b + (size_t)c * PLANE4;
#pragma unroll
        for (int k = 0; k < 4; k++) {
            if (cval[k]) {
                float4 v = __ldcs(base + coff[k]);
                acc[k].x += v.x; acc[k].y += v.y; acc[k].z += v.z; acc[k].w += v.w;
            }
        }
        if (eval) eacc += __ldcs(xsb + (size_t)c * PLANE + eoff);
    }

#pragma unroll
    for (int k = 0; k < 4; k++) {
        if (csm[k] >= 0) {
            float4 a = cval[k] ? acc[k] : make_float4(0.f, 0.f, 0.f, 0.f);
            Csh[csm[k] + 0] = a.x;
            Csh[csm[k] + 1] = a.y;
            Csh[csm[k] + 2] = a.z;
            Csh[csm[k] + 3] = a.w;
        }
    }
    if (eact) Csh[esm] = eval ? eacc : 0.f;

    __syncthreads();

    // ---------------- Phase 2: stencil + broadcast to 128 channels ----------------
    float4* out4b = reinterpret_cast<float4*>(out) + (size_t)b * COUT * PLANE4;

#pragma unroll
    for (int k = 0; k < 4; k++) {
        int s = tid + k * NT;
        if (s < NP2) {
            int ii = s / (TC / 4);
            int j4 = s - ii * (TC / 4);
            int i  = ii + 1;                 // smem row
            int cb = 1 + 4 * j4;             // smem col of first output elem

            const float* rowC = Csh + i * SS;
            const float* rowU = rowC - SS;
            const float* rowD = rowC + SS;

            float lm = rowC[cb - 1];
            float v0 = rowC[cb + 0], v1 = rowC[cb + 1];
            float v2 = rowC[cb + 2], v3 = rowC[cb + 3];
            float rp = rowC[cb + 4];

            float4 r;
            r.x = rowU[cb + 0] + rowD[cb + 0] + lm + v1 + v0;
            r.y = rowU[cb + 1] + rowD[cb + 1] + v0 + v2 + v1;
            r.z = rowU[cb + 2] + rowD[cb + 2] + v1 + v3 + v2;
            r.w = rowU[cb + 3] + rowD[cb + 3] + v2 + rp + v3;

            int gr = r0 + ii;
            float4* op = out4b + gr * (Ww / 4) + (c0 >> 2) + j4;
#pragma unroll 4
            for (int o = 0; o < COUT; o++) {
                float bo = sb[o];
                float4 v = make_float4(r.x + bo, r.y + bo, r.z + bo, r.w + bo);
                __stcs(op + (size_t)o * PLANE4, v);
            }
        }
    }
}

extern "C" void kernel_launch(void* const* d_in, const int* in_sizes, int n_in,
                              void* d_out, int out_size) {
    const float* x    = (const float*)d_in[0];   // [16,128,224,224] f32
    const float* bias = (const float*)d_in[2];   // [128] f32
    float* out = (float*)d_out;                  // [16,128,224,224] f32

    fused_cross_conv<<<BATCH * 16, NT>>>(x, bias, out);
}